// round 14
// baseline (speedup 1.0000x reference)
#include <cuda_runtime.h>
#include <stdint.h>

// Problem shape (fixed by the dataset)
#define M_DIM 1024
#define K_DIM 2048
#define N_DIM 2048

// Tiling: 16 x 64 output tile per CTA, 128 threads (4 warps).
// Each warp: 4 m-rows x 64 n-cols (lane owns n and n+32) -> accA[4]+accB[4].
// Small tiles shrink the end-of-kernel quantization tail (2048 tiles,
// 4.49 per persistent CTA, vs 2.25 before).
#define BM 16
#define BN 64
#define KT 32
#define NT (K_DIM / KT)        // 64 k-tiles
#define NUM_TILES 2048         // 64 m-tiles x 32 n-tiles
#define PERSIST_CTAS 456       // 3 per SM on 152 SMs

#define SA_STRIDE 32           // dense; warp-uniform broadcast reads
#define SA_BUF (BM * SA_STRIDE)          // 512 B
#define SW_STRIDE 48           // 32 data + 16 pad; /16=3 odd -> LDS.128 min phases
#define SW_BUF (BN * SW_STRIDE)          // 3072 B

#define SMEM_BYTES (65536 + 2 * SA_BUF + 2 * SW_BUF)   // 72704 -> occ 3

// Scratch (allocation-free __device__ globals)
__device__ uint8_t g_A8[M_DIM * K_DIM];
__device__ uint8_t g_W8[N_DIM * K_DIM];
__device__ uint8_t g_LUT8[65536];
__device__ unsigned int g_tileCtr;

static __device__ __forceinline__ uint8_t clamp_u8(float v) {
    int c = (int)v;
    c = c < 0 ? 0 : (c > 255 ? 255 : c);
    return (uint8_t)c;
}

__global__ void quantA_kernel(const float* __restrict__ src) {
    int i = blockIdx.x * blockDim.x + threadIdx.x;   // groups of 4
    if (i < M_DIM * K_DIM / 4) {
        float4 v = ((const float4*)src)[i];
        uchar4 b;
        b.x = clamp_u8(v.x); b.y = clamp_u8(v.y);
        b.z = clamp_u8(v.z); b.w = clamp_u8(v.w);
        ((uchar4*)g_A8)[i] = b;
    }
}

__global__ void quantW_kernel(const float* __restrict__ src) {
    int i = blockIdx.x * blockDim.x + threadIdx.x;
    if (i < N_DIM * K_DIM / 4) {
        float4 v = ((const float4*)src)[i];
        uchar4 b;
        b.x = clamp_u8(v.x); b.y = clamp_u8(v.y);
        b.z = clamp_u8(v.z); b.w = clamp_u8(v.w);
        ((uchar4*)g_W8)[i] = b;
    }
}

__global__ void quantLUT_kernel(const int* __restrict__ lut) {
    int i = blockIdx.x * blockDim.x + threadIdx.x;   // groups of 4
    if (i == 0) g_tileCtr = 0;                       // reset queue every launch
    if (i < 65536 / 4) {
        int4 v = ((const int4*)lut)[i];
        uchar4 b;
        b.x = (uint8_t)v.x; b.y = (uint8_t)v.y;
        b.z = (uint8_t)v.z; b.w = (uint8_t)v.w;
        ((uchar4*)g_LUT8)[i] = b;
    }
}

// Index build: ((aword shift)&0xFF00)|w  -> SHF+LOP3 per index.
#define GATHER4(accv, aword, wv0, wv1, wv2, wv3)             \
    do {                                                     \
        uint32_t _i0 = (((aword) << 8)  & 0xFF00u) | (wv0);  \
        uint32_t _i1 = (( aword)        & 0xFF00u) | (wv1);  \
        uint32_t _i2 = (((aword) >> 8)  & 0xFF00u) | (wv2);  \
        uint32_t _i3 = (((aword) >> 16) & 0xFF00u) | (wv3);  \
        accv += sLUT[_i0];                                   \
        accv += sLUT[_i1];                                   \
        accv += sLUT[_i2];                                   \
        accv += sLUT[_i3];                                   \
    } while (0)

// One k-group of 8: a codes from two broadcast words, w codes from two words.
#define KGROUP8(alo, ahi, wlo, whi, accv)                                  \
    do {                                                                   \
        uint32_t _w0 =  (wlo)        & 255u, _w1 = ((wlo) >> 8)  & 255u;   \
        uint32_t _w2 = ((wlo) >> 16) & 255u, _w3 =  (wlo) >> 24;           \
        uint32_t _w4 =  (whi)        & 255u, _w5 = ((whi) >> 8)  & 255u;   \
        uint32_t _w6 = ((whi) >> 16) & 255u, _w7 =  (whi) >> 24;           \
        GATHER4(accv, alo, _w0, _w1, _w2, _w3);                            \
        GATHER4(accv, ahi, _w4, _w5, _w6, _w7);                            \
    } while (0)

// Persistent LUT-GEMM kernel: 456 CTAs, 128 threads, occ 3 -> 12 warps/SM.
__global__ void __launch_bounds__(128, 3)
lut_gemm_kernel(const float* __restrict__ bias,
                float* __restrict__ out) {
    extern __shared__ uint8_t smem[];
    uint8_t* sLUT = smem;                     // 65536 B
    uint8_t* sA   = smem + 65536;             // [2][BM][SA_STRIDE]
    uint8_t* sW   = sA + 2 * SA_BUF;          // [2][BN][SW_STRIDE]
    __shared__ int sTile;

    const int tid  = threadIdx.x;
    const int lane = tid & 31;
    const int warp = tid >> 5;                // 0..3 -> m-group of 4 rows

    // Copy pre-quantized LUT (64KB) into shared ONCE per persistent CTA.
    for (int i = tid; i < 65536 / 16; i += 128) {
        ((uint4*)sLUT)[i] = ((const uint4*)g_LUT8)[i];
    }

    const int mBase = warp * 4;               // warp's first row within tile

    // Staging roles:
    // A: 128 threads cover 16 rows x 8 words of 4B (512 B per buffer).
    const int arow   = tid >> 3;
    const int achunk = (tid & 7) * 4;
    uint8_t* sAst = sA + arow * SA_STRIDE + achunk;
    // W: 128 threads cover 64 rows x 2 chunks of 16B.
    const int wrow   = tid >> 1;
    const int wchunk = (tid & 1) * 16;
    uint8_t* sWst = sW + wrow * SW_STRIDE + wchunk;

    const uint8_t* sArow  = sA + mBase * SA_STRIDE;
    const uint8_t* sWrowA = sW + lane * SW_STRIDE;          // n = n0+lane
    const uint8_t* sWrowB = sW + (lane + 32) * SW_STRIDE;   // n = n0+lane+32

    for (;;) {
        if (tid == 0) sTile = (int)atomicAdd(&g_tileCtr, 1u);
        __syncthreads();                      // broadcast tile; fences smem reuse
        const int tileId = sTile;
        if (tileId >= NUM_TILES) break;       // uniform exit

        const int m0 = (tileId >> 5) * BM;    // 64 tile rows
        const int n0 = (tileId & 31) * BN;    // 32 tile cols

        int accA[4], accB[4];
#pragma unroll
        for (int i = 0; i < 4; i++) { accA[i] = 0; accB[i] = 0; }

        const uint8_t* gAst = g_A8 + ((size_t)(m0 + arow)) * K_DIM + achunk;
        const uint8_t* gWst = g_W8 + ((size_t)(n0 + wrow)) * K_DIM + wchunk;

        // ---- prologue: stage tile 0 into buffer 0 ----
        {
            uint32_t ra = *(const uint32_t*)gAst;
            *(uint32_t*)sAst = ra;
            uint4 rw = *(const uint4*)gWst;
            *(uint4*)sWst = rw;
        }
        __syncthreads();

        for (int t = 0; t < NT; t++) {
            // Prefetch tile t+1 into registers (clamped on last iter).
            const int kn = ((t + 1 < NT) ? (t + 1) : t) * KT;
            uint32_t ra_n = *(const uint32_t*)(gAst + kn);
            uint4    rw_n = *(const uint4*)(gWst + kn);

            const int bufo = (t & 1);
            const uint8_t* sAbuf  = sArow  + bufo * SA_BUF;
            const uint8_t* sWbufA = sWrowA + bufo * SW_BUF;
            const uint8_t* sWbufB = sWrowB + bufo * SW_BUF;

            // Two 16-k halves: keeps live W regs at 8 (wa + wb).
#pragma unroll
            for (int h = 0; h < 2; h++) {
                uint4 wa = *(const uint4*)(sWbufA + h * 16);   // n,    16 k
                uint4 wb = *(const uint4*)(sWbufB + h * 16);   // n+32, 16 k

#pragma unroll
                for (int m = 0; m < 4; m++) {
                    // One warp-uniform LDS.128 broadcast: 16 a-codes, feeds
                    // 32 lookups (16 k x 2 n-columns).
                    uint4 av = *(const uint4*)(sAbuf + m * SA_STRIDE + h * 16);
                    KGROUP8(av.x, av.y, wa.x, wa.y, accA[m]);
                    KGROUP8(av.z, av.w, wa.z, wa.w, accA[m]);
                    KGROUP8(av.x, av.y, wb.x, wb.y, accB[m]);
                    KGROUP8(av.z, av.w, wb.z, wb.w, accB[m]);
                }
            }

            // Stage tile t+1 into the other buffer, then sync.
            const int nbufo = ((t + 1) & 1);
            *(uint32_t*)(sAst + nbufo * SA_BUF) = ra_n;
            *(uint4*)(sWst + nbufo * SW_BUF) = rw_n;
            __syncthreads();
        }

        const float bA = bias[n0 + lane];
        const float bB = bias[n0 + 32 + lane];
#pragma unroll
        for (int m = 0; m < 4; m++) {
            const size_t row = (size_t)(m0 + mBase + m) * N_DIM;
            out[row + n0 + lane]      = (float)accA[m] + bA;
            out[row + n0 + 32 + lane] = (float)accB[m] + bB;
        }
        // loop back: the atomic-broadcast __syncthreads fences buffer reuse
    }
}

extern "C" void kernel_launch(void* const* d_in, const int* in_sizes, int n_in,
                              void* d_out, int out_size) {
    const float* input  = (const float*)d_in[0];  // [M, K] codes as f32
    const float* weight = (const float*)d_in[1];  // [N, K] codes as f32
    const float* bias   = (const float*)d_in[2];  // [N]
    const int*   lut    = (const int*)d_in[3];    // [256*256]
    float* out = (float*)d_out;

    (void)in_sizes; (void)n_in; (void)out_size;

    // Opt-in to >48KB dynamic smem (idempotent; capture-safe)
    cudaFuncSetAttribute((const void*)lut_gemm_kernel,
                         cudaFuncAttributeMaxDynamicSharedMemorySize, SMEM_BYTES);

    quantA_kernel<<<(M_DIM * K_DIM / 4 + 255) / 256, 256>>>(input);
    quantW_kernel<<<(N_DIM * K_DIM / 4 + 255) / 256, 256>>>(weight);
    quantLUT_kernel<<<(65536 / 4 + 255) / 256, 256>>>(lut);  // also resets queue

    lut_gemm_kernel<<<PERSIST_CTAS, 128, SMEM_BYTES>>>(bias, out);
}

// round 15
// speedup vs baseline: 1.0305x; 1.0305x over previous
#include <cuda_runtime.h>
#include <stdint.h>

// Problem shape (fixed by the dataset)
#define M_DIM 1024
#define K_DIM 2048
#define N_DIM 2048

// Tiling: 32 x 64 output tile, 128 threads (4 warps) -- R11's verified shape.
// Each warp: 8 m-rows x 64 n-cols (lane owns n and n+32) -> accA[8]+accB[8].
// Work unit = (m-tile, n-tile, k-half): 2048 units, K split in halves of 1024.
// Partial sums are ints -> atomicAdd into scratch (deterministic), epilogue adds bias.
#define BM 32
#define BN 64
#define KT 32
#define NT_UNIT 32             // k-tiles per unit (half of K)
#define NUM_UNITS 2048         // 32 m-tiles x 32 n-tiles x 2 k-halves
#define PERSIST_CTAS 456       // 3 per SM on 152 SMs

#define SA_STRIDE 32           // dense; warp-uniform broadcast reads
#define SA_BUF (BM * SA_STRIDE)          // 1024 B
#define SW_STRIDE 48           // 32 data + 16 pad; /16=3 odd -> LDS.128 min phases
#define SW_BUF (BN * SW_STRIDE)          // 3072 B

#define SMEM_BYTES (65536 + 2 * SA_BUF + 2 * SW_BUF)   // 73728 -> occ 3

// Scratch (allocation-free __device__ globals)
__device__ uint8_t g_A8[M_DIM * K_DIM];
__device__ uint8_t g_W8[N_DIM * K_DIM];
__device__ uint8_t g_LUT8[65536];
__device__ int     g_Pacc[M_DIM * N_DIM];   // 8MB int partial accumulator
__device__ unsigned int g_tileCtr;

static __device__ __forceinline__ uint8_t clamp_u8(float v) {
    int c = (int)v;
    c = c < 0 ? 0 : (c > 255 ? 255 : c);
    return (uint8_t)c;
}

__global__ void quantA_kernel(const float* __restrict__ src) {
    int i = blockIdx.x * blockDim.x + threadIdx.x;   // groups of 4
    if (i < M_DIM * K_DIM / 4) {
        float4 v = ((const float4*)src)[i];
        uchar4 b;
        b.x = clamp_u8(v.x); b.y = clamp_u8(v.y);
        b.z = clamp_u8(v.z); b.w = clamp_u8(v.w);
        ((uchar4*)g_A8)[i] = b;
    }
}

__global__ void quantW_kernel(const float* __restrict__ src) {
    int i = blockIdx.x * blockDim.x + threadIdx.x;
    if (i < N_DIM * K_DIM / 4) {
        float4 v = ((const float4*)src)[i];
        uchar4 b;
        b.x = clamp_u8(v.x); b.y = clamp_u8(v.y);
        b.z = clamp_u8(v.z); b.w = clamp_u8(v.w);
        ((uchar4*)g_W8)[i] = b;
    }
}

__global__ void quantLUT_kernel(const int* __restrict__ lut) {
    int i = blockIdx.x * blockDim.x + threadIdx.x;   // groups of 4
    if (i == 0) g_tileCtr = 0;                       // reset queue every launch
    if (i < 65536 / 4) {
        int4 v = ((const int4*)lut)[i];
        uchar4 b;
        b.x = (uint8_t)v.x; b.y = (uint8_t)v.y;
        b.z = (uint8_t)v.z; b.w = (uint8_t)v.w;
        ((uchar4*)g_LUT8)[i] = b;
    }
}

// Zero the partial accumulator each launch (graph-replay safe).
__global__ void zeroP_kernel() {
    int i = blockIdx.x * blockDim.x + threadIdx.x;   // groups of 4
    if (i < M_DIM * N_DIM / 4) {
        ((int4*)g_Pacc)[i] = make_int4(0, 0, 0, 0);
    }
}

// Epilogue: out = (float)partial + bias. Vectorized by 4 columns.
__global__ void finishO_kernel(const float* __restrict__ bias,
                               float* __restrict__ out) {
    int i = blockIdx.x * blockDim.x + threadIdx.x;   // groups of 4 cols
    if (i < M_DIM * N_DIM / 4) {
        int4   p = ((const int4*)g_Pacc)[i];
        float4 b = ((const float4*)bias)[i & (N_DIM / 4 - 1)];
        float4 o;
        o.x = (float)p.x + b.x;
        o.y = (float)p.y + b.y;
        o.z = (float)p.z + b.z;
        o.w = (float)p.w + b.w;
        ((float4*)out)[i] = o;
    }
}

// Index build: ((aword shift)&0xFF00)|w  -> SHF+LOP3 per index.
#define GATHER4(accv, aword, wv0, wv1, wv2, wv3)             \
    do {                                                     \
        uint32_t _i0 = (((aword) << 8)  & 0xFF00u) | (wv0);  \
        uint32_t _i1 = (( aword)        & 0xFF00u) | (wv1);  \
        uint32_t _i2 = (((aword) >> 8)  & 0xFF00u) | (wv2);  \
        uint32_t _i3 = (((aword) >> 16) & 0xFF00u) | (wv3);  \
        accv += sLUT[_i0];                                   \
        accv += sLUT[_i1];                                   \
        accv += sLUT[_i2];                                   \
        accv += sLUT[_i3];                                   \
    } while (0)

// One k-group of 8: a codes from two broadcast words, w codes from two words.
#define KGROUP8(alo, ahi, wlo, whi, accv)                                  \
    do {                                                                   \
        uint32_t _w0 =  (wlo)        & 255u, _w1 = ((wlo) >> 8)  & 255u;   \
        uint32_t _w2 = ((wlo) >> 16) & 255u, _w3 =  (wlo) >> 24;           \
        uint32_t _w4 =  (whi)        & 255u, _w5 = ((whi) >> 8)  & 255u;   \
        uint32_t _w6 = ((whi) >> 16) & 255u, _w7 =  (whi) >> 24;           \
        GATHER4(accv, alo, _w0, _w1, _w2, _w3);                            \
        GATHER4(accv, ahi, _w4, _w5, _w6, _w7);                            \
    } while (0)

// Persistent LUT-GEMM kernel: 456 CTAs, 128 threads, occ 3 -> 12 warps/SM.
// Inner k-tile body is byte-identical to the R11 winner.
__global__ void __launch_bounds__(128, 3)
lut_gemm_kernel(void) {
    extern __shared__ uint8_t smem[];
    uint8_t* sLUT = smem;                     // 65536 B
    uint8_t* sA   = smem + 65536;             // [2][BM][SA_STRIDE]
    uint8_t* sW   = sA + 2 * SA_BUF;          // [2][BN][SW_STRIDE]
    __shared__ int sTile;

    const int tid  = threadIdx.x;
    const int lane = tid & 31;
    const int warp = tid >> 5;                // 0..3 -> m-group of 8 rows

    // Copy pre-quantized LUT (64KB) into shared ONCE per persistent CTA.
    for (int i = tid; i < 65536 / 16; i += 128) {
        ((uint4*)sLUT)[i] = ((const uint4*)g_LUT8)[i];
    }

    const int mBase = warp * 8;               // warp's first row within tile

    // Staging roles:
    // A: threads 0..63 cover 32 rows x 2 chunks of 16B.
    const int arow   = tid >> 1;
    const int achunk = (tid & 1) * 16;
    uint8_t* sAst = sA + arow * SA_STRIDE + achunk;
    // W: all 128 threads cover 64 rows x 2 chunks of 16B.
    const int wrow   = tid >> 1;
    const int wchunk = (tid & 1) * 16;
    uint8_t* sWst = sW + wrow * SW_STRIDE + wchunk;

    const uint8_t* sArow  = sA + mBase * SA_STRIDE;
    const uint8_t* sWrowA = sW + lane * SW_STRIDE;          // n = n0+lane
    const uint8_t* sWrowB = sW + (lane + 32) * SW_STRIDE;   // n = n0+lane+32

    for (;;) {
        if (tid == 0) sTile = (int)atomicAdd(&g_tileCtr, 1u);
        __syncthreads();                      // broadcast unit; fences smem reuse
        const int unitId = sTile;
        if (unitId >= NUM_UNITS) break;       // uniform exit

        const int kh = unitId >> 10;          // k-half: 0 or 1
        const int mn = unitId & 1023;
        const int m0 = (mn >> 5) * BM;        // 32 tile rows
        const int n0 = (mn & 31) * BN;        // 32 tile cols
        const int kbase = kh * (K_DIM / 2);   // 0 or 1024

        int accA[8], accB[8];
#pragma unroll
        for (int i = 0; i < 8; i++) { accA[i] = 0; accB[i] = 0; }

        const uint8_t* gAst = g_A8 + ((size_t)(m0 + arow)) * K_DIM + kbase + achunk;
        const uint8_t* gWst = g_W8 + ((size_t)(n0 + wrow)) * K_DIM + kbase + wchunk;

        // ---- prologue: stage k-tile 0 into buffer 0 ----
        {
            if (tid < 64) {
                uint4 ra = *(const uint4*)gAst;
                *(uint4*)sAst = ra;
            }
            uint4 rw = *(const uint4*)gWst;
            *(uint4*)sWst = rw;
        }
        __syncthreads();

        for (int t = 0; t < NT_UNIT; t++) {
            // Prefetch k-tile t+1 into registers (clamped on last iter).
            const int kn = ((t + 1 < NT_UNIT) ? (t + 1) : t) * KT;
            uint4 ra_n;
            if (tid < 64) ra_n = *(const uint4*)(gAst + kn);
            uint4 rw_n = *(const uint4*)(gWst + kn);

            const int bufo = (t & 1);
            const uint8_t* sAbuf  = sArow  + bufo * SA_BUF;
            const uint8_t* sWbufA = sWrowA + bufo * SW_BUF;
            const uint8_t* sWbufB = sWrowB + bufo * SW_BUF;

            // Two 16-k halves: keeps live W regs at 8 (wa + wb).
#pragma unroll
            for (int h = 0; h < 2; h++) {
                uint4 wa = *(const uint4*)(sWbufA + h * 16);   // n,    16 k
                uint4 wb = *(const uint4*)(sWbufB + h * 16);   // n+32, 16 k

#pragma unroll
                for (int m = 0; m < 8; m++) {
                    // One warp-uniform LDS.128 broadcast: 16 a-codes, feeds
                    // 32 lookups (16 k x 2 n-columns).
                    uint4 av = *(const uint4*)(sAbuf + m * SA_STRIDE + h * 16);
                    KGROUP8(av.x, av.y, wa.x, wa.y, accA[m]);
                    KGROUP8(av.z, av.w, wa.z, wa.w, accA[m]);
                    KGROUP8(av.x, av.y, wb.x, wb.y, accB[m]);
                    KGROUP8(av.z, av.w, wb.z, wb.w, accB[m]);
                }
            }

            // Stage k-tile t+1 into the other buffer, then sync.
            const int nbufo = ((t + 1) & 1);
            if (tid < 64) *(uint4*)(sAst + nbufo * SA_BUF) = ra_n;
            *(uint4*)(sWst + nbufo * SW_BUF) = rw_n;
            __syncthreads();
        }

        // Epilogue: deterministic int atomic accumulate of this k-half.
#pragma unroll
        for (int m = 0; m < 8; m++) {
            int* rowp = g_Pacc + (size_t)(m0 + mBase + m) * N_DIM;
            atomicAdd(rowp + n0 + lane,      accA[m]);
            atomicAdd(rowp + n0 + 32 + lane, accB[m]);
        }
        // loop back: the atomic-broadcast __syncthreads fences buffer reuse
    }
}

extern "C" void kernel_launch(void* const* d_in, const int* in_sizes, int n_in,
                              void* d_out, int out_size) {
    const float* input  = (const float*)d_in[0];  // [M, K] codes as f32
    const float* weight = (const float*)d_in[1];  // [N, K] codes as f32
    const float* bias   = (const float*)d_in[2];  // [N]
    const int*   lut    = (const int*)d_in[3];    // [256*256]
    float* out = (float*)d_out;

    (void)in_sizes; (void)n_in; (void)out_size;

    // Opt-in to >48KB dynamic smem (idempotent; capture-safe)
    cudaFuncSetAttribute((const void*)lut_gemm_kernel,
                         cudaFuncAttributeMaxDynamicSharedMemorySize, SMEM_BYTES);

    quantA_kernel<<<(M_DIM * K_DIM / 4 + 255) / 256, 256>>>(input);
    quantW_kernel<<<(N_DIM * K_DIM / 4 + 255) / 256, 256>>>(weight);
    quantLUT_kernel<<<(65536 / 4 + 255) / 256, 256>>>(lut);  // also resets queue
    zeroP_kernel<<<(M_DIM * N_DIM / 4 + 255) / 256, 256>>>();

    lut_gemm_kernel<<<PERSIST_CTAS, 128, SMEM_BYTES>>>();

    finishO_kernel<<<(M_DIM * N_DIM / 4 + 255) / 256, 256>>>(bias, out);
}

// round 16
// speedup vs baseline: 1.4794x; 1.4356x over previous
#include <cuda_runtime.h>
#include <stdint.h>

// Problem shape (fixed by the dataset)
#define M_DIM 1024
#define K_DIM 2048
#define N_DIM 2048

// Tiling: 32 x 64 output tile per CTA, 128 threads (4 warps) -- R11 verified.
// Each warp: 8 m-rows x 64 n-cols (lane owns n and n+32) -> accA[8]+accB[8].
#define BM 32
#define BN 64
#define KT 32
#define NT (K_DIM / KT)        // 64 k-tiles
#define NUM_TILES 1024         // 32 m-tiles x 32 n-tiles
#define PERSIST_CTAS 456       // 3 per SM on 152 SMs

#define SA_STRIDE 32           // dense; warp-uniform broadcast reads
#define SA_BUF (BM * SA_STRIDE)          // 1024 B
#define SW_STRIDE 48           // 32 data + 16 pad; /16=3 odd -> LDS.128 min phases
#define SW_BUF (BN * SW_STRIDE)          // 3072 B

#define SMEM_BYTES (65536 + 2 * SA_BUF + 2 * SW_BUF)   // 73728 -> occ 3

// Scratch (allocation-free __device__ globals)
__device__ uint8_t g_A8[M_DIM * K_DIM];
__device__ uint8_t g_W8[N_DIM * K_DIM];
__device__ uint8_t g_LUT8[65536];
__device__ unsigned int g_tileCtr;

static __device__ __forceinline__ uint8_t clamp_u8(float v) {
    int c = (int)v;
    c = c < 0 ? 0 : (c > 255 ? 255 : c);
    return (uint8_t)c;
}

// Merged prep: one kernel quantizes A, W, and LUT (grid partitions the ranges,
// all three streams overlap on HBM) and resets the tile queue.
#define A_GROUPS (M_DIM * K_DIM / 4)             // 524288
#define W_GROUPS (N_DIM * K_DIM / 4)             // 1048576
#define L_GROUPS (65536 / 4)                     // 16384
#define PREP_GROUPS (A_GROUPS + W_GROUPS + L_GROUPS)

__global__ void prep_kernel(const float* __restrict__ inA,
                            const float* __restrict__ inW,
                            const int*   __restrict__ lut) {
    int i = blockIdx.x * blockDim.x + threadIdx.x;
    if (i == 0) g_tileCtr = 0;                   // reset queue every launch
    if (i < A_GROUPS) {
        float4 v = ((const float4*)inA)[i];
        uchar4 b;
        b.x = clamp_u8(v.x); b.y = clamp_u8(v.y);
        b.z = clamp_u8(v.z); b.w = clamp_u8(v.w);
        ((uchar4*)g_A8)[i] = b;
    } else if (i < A_GROUPS + W_GROUPS) {
        int j = i - A_GROUPS;
        float4 v = ((const float4*)inW)[j];
        uchar4 b;
        b.x = clamp_u8(v.x); b.y = clamp_u8(v.y);
        b.z = clamp_u8(v.z); b.w = clamp_u8(v.w);
        ((uchar4*)g_W8)[j] = b;
    } else if (i < PREP_GROUPS) {
        int j = i - A_GROUPS - W_GROUPS;
        int4 v = ((const int4*)lut)[j];
        uchar4 b;
        b.x = (uint8_t)v.x; b.y = (uint8_t)v.y;
        b.z = (uint8_t)v.z; b.w = (uint8_t)v.w;
        ((uchar4*)g_LUT8)[j] = b;
    }
}

// Index build: ((aword shift)&0xFF00)|w  -> SHF+LOP3 per index.
#define GATHER4(accv, aword, wv0, wv1, wv2, wv3)             \
    do {                                                     \
        uint32_t _i0 = (((aword) << 8)  & 0xFF00u) | (wv0);  \
        uint32_t _i1 = (( aword)        & 0xFF00u) | (wv1);  \
        uint32_t _i2 = (((aword) >> 8)  & 0xFF00u) | (wv2);  \
        uint32_t _i3 = (((aword) >> 16) & 0xFF00u) | (wv3);  \
        accv += sLUT[_i0];                                   \
        accv += sLUT[_i1];                                   \
        accv += sLUT[_i2];                                   \
        accv += sLUT[_i3];                                   \
    } while (0)

// One k-group of 8: a codes from two broadcast words, w codes from two words.
#define KGROUP8(alo, ahi, wlo, whi, accv)                                  \
    do {                                                                   \
        uint32_t _w0 =  (wlo)        & 255u, _w1 = ((wlo) >> 8)  & 255u;   \
        uint32_t _w2 = ((wlo) >> 16) & 255u, _w3 =  (wlo) >> 24;           \
        uint32_t _w4 =  (whi)        & 255u, _w5 = ((whi) >> 8)  & 255u;   \
        uint32_t _w6 = ((whi) >> 16) & 255u, _w7 =  (whi) >> 24;           \
        GATHER4(accv, alo, _w0, _w1, _w2, _w3);                            \
        GATHER4(accv, ahi, _w4, _w5, _w6, _w7);                            \
    } while (0)

// Persistent LUT-GEMM kernel: 456 CTAs, 128 threads, occ 3 -> 12 warps/SM.
// Byte-identical compute structure to the R11 winner (977us main kernel).
__global__ void __launch_bounds__(128, 3)
lut_gemm_kernel(const float* __restrict__ bias,
                float* __restrict__ out) {
    extern __shared__ uint8_t smem[];
    uint8_t* sLUT = smem;                     // 65536 B
    uint8_t* sA   = smem + 65536;             // [2][BM][SA_STRIDE]
    uint8_t* sW   = sA + 2 * SA_BUF;          // [2][BN][SW_STRIDE]
    __shared__ int sTile;

    const int tid  = threadIdx.x;
    const int lane = tid & 31;
    const int warp = tid >> 5;                // 0..3 -> m-group of 8 rows

    // Copy pre-quantized LUT (64KB) into shared ONCE per persistent CTA.
    for (int i = tid; i < 65536 / 16; i += 128) {
        ((uint4*)sLUT)[i] = ((const uint4*)g_LUT8)[i];
    }

    const int mBase = warp * 8;               // warp's first row within tile

    // Staging roles:
    // A: threads 0..63 cover 32 rows x 2 chunks of 16B.
    const int arow   = tid >> 1;
    const int achunk = (tid & 1) * 16;
    uint8_t* sAst = sA + arow * SA_STRIDE + achunk;
    // W: all 128 threads cover 64 rows x 2 chunks of 16B.
    const int wrow   = tid >> 1;
    const int wchunk = (tid & 1) * 16;
    uint8_t* sWst = sW + wrow * SW_STRIDE + wchunk;

    const uint8_t* sArow  = sA + mBase * SA_STRIDE;
    const uint8_t* sWrowA = sW + lane * SW_STRIDE;          // n = n0+lane
    const uint8_t* sWrowB = sW + (lane + 32) * SW_STRIDE;   // n = n0+lane+32

    for (;;) {
        if (tid == 0) sTile = (int)atomicAdd(&g_tileCtr, 1u);
        __syncthreads();                      // broadcast tile; fences smem reuse
        const int tileId = sTile;
        if (tileId >= NUM_TILES) break;       // uniform exit

        const int m0 = (tileId >> 5) * BM;    // 32 tile rows
        const int n0 = (tileId & 31) * BN;    // 32 tile cols

        int accA[8], accB[8];
#pragma unroll
        for (int i = 0; i < 8; i++) { accA[i] = 0; accB[i] = 0; }

        const uint8_t* gAst = g_A8 + ((size_t)(m0 + arow)) * K_DIM + achunk;
        const uint8_t* gWst = g_W8 + ((size_t)(n0 + wrow)) * K_DIM + wchunk;

        // ---- prologue: stage tile 0 into buffer 0 ----
        {
            if (tid < 64) {
                uint4 ra = *(const uint4*)gAst;
                *(uint4*)sAst = ra;
            }
            uint4 rw = *(const uint4*)gWst;
            *(uint4*)sWst = rw;
        }
        __syncthreads();

        for (int t = 0; t < NT; t++) {
            // Prefetch tile t+1 into registers (clamped on last iter).
            const int kn = ((t + 1 < NT) ? (t + 1) : t) * KT;
            uint4 ra_n;
            if (tid < 64) ra_n = *(const uint4*)(gAst + kn);
            uint4 rw_n = *(const uint4*)(gWst + kn);

            const int bufo = (t & 1);
            const uint8_t* sAbuf  = sArow  + bufo * SA_BUF;
            const uint8_t* sWbufA = sWrowA + bufo * SW_BUF;
            const uint8_t* sWbufB = sWrowB + bufo * SW_BUF;

            // Two 16-k halves: keeps live W regs at 8 (wa + wb).
#pragma unroll
            for (int h = 0; h < 2; h++) {
                uint4 wa = *(const uint4*)(sWbufA + h * 16);   // n,    16 k
                uint4 wb = *(const uint4*)(sWbufB + h * 16);   // n+32, 16 k

#pragma unroll
                for (int m = 0; m < 8; m++) {
                    // One warp-uniform LDS.128 broadcast: 16 a-codes, feeds
                    // 32 lookups (16 k x 2 n-columns).
                    uint4 av = *(const uint4*)(sAbuf + m * SA_STRIDE + h * 16);
                    KGROUP8(av.x, av.y, wa.x, wa.y, accA[m]);
                    KGROUP8(av.z, av.w, wa.z, wa.w, accA[m]);
                    KGROUP8(av.x, av.y, wb.x, wb.y, accB[m]);
                    KGROUP8(av.z, av.w, wb.z, wb.w, accB[m]);
                }
            }

            // Stage tile t+1 into the other buffer, then sync.
            const int nbufo = ((t + 1) & 1);
            if (tid < 64) *(uint4*)(sAst + nbufo * SA_BUF) = ra_n;
            *(uint4*)(sWst + nbufo * SW_BUF) = rw_n;
            __syncthreads();
        }

        const float bA = bias[n0 + lane];
        const float bB = bias[n0 + 32 + lane];
#pragma unroll
        for (int m = 0; m < 8; m++) {
            const size_t row = (size_t)(m0 + mBase + m) * N_DIM;
            out[row + n0 + lane]      = (float)accA[m] + bA;
            out[row + n0 + 32 + lane] = (float)accB[m] + bB;
        }
        // loop back: the atomic-broadcast __syncthreads fences buffer reuse
    }
}

extern "C" void kernel_launch(void* const* d_in, const int* in_sizes, int n_in,
                              void* d_out, int out_size) {
    const float* input  = (const float*)d_in[0];  // [M, K] codes as f32
    const float* weight = (const float*)d_in[1];  // [N, K] codes as f32
    const float* bias   = (const float*)d_in[2];  // [N]
    const int*   lut    = (const int*)d_in[3];    // [256*256]
    float* out = (float*)d_out;

    (void)in_sizes; (void)n_in; (void)out_size;

    // Opt-in to >48KB dynamic smem (idempotent; capture-safe)
    cudaFuncSetAttribute((const void*)lut_gemm_kernel,
                         cudaFuncAttributeMaxDynamicSharedMemorySize, SMEM_BYTES);

    // Single merged prep launch: quantize A, W, LUT; reset tile queue.
    prep_kernel<<<(PREP_GROUPS + 255) / 256, 256>>>(input, weight, lut);

    lut_gemm_kernel<<<PERSIST_CTAS, 128, SMEM_BYTES>>>(bias, out);
}

// round 17
// speedup vs baseline: 1.6939x; 1.1450x over previous
#include <cuda_runtime.h>
#include <stdint.h>

// Problem shape (fixed by the dataset)
#define M_DIM 1024
#define K_DIM 2048
#define N_DIM 2048

// Tiling: 32 x 64 output tile per CTA, 128 threads (4 warps).
// Each warp: 8 m-rows x 64 n-cols (lane owns n and n+32) -> accA[8]+accB[8].
// A codes: one LDS.128 broadcast per (m, 16k-half) -> feeds 32 lookups.
#define BM 32
#define BN 64
#define KT 32
#define NT (K_DIM / KT)        // 64 k-tiles
#define NUM_TILES 1024         // 32 m-tiles x 32 n-tiles
#define PERSIST_CTAS 456       // 3 per SM on 152 SMs

#define SA_STRIDE 32           // dense; broadcast reads
#define SA_BUF (BM * SA_STRIDE)          // 1024 B
#define SW_STRIDE 48           // 32 data + 16 pad; /16=3 odd -> LDS.128 min phases
#define SW_BUF (BN * SW_STRIDE)          // 3072 B

#define SMEM_BYTES (65536 + 2 * SA_BUF + 2 * SW_BUF)   // 73728 -> occ 3

// Scratch (allocation-free __device__ globals)
__device__ uint8_t g_A8[M_DIM * K_DIM];
__device__ uint8_t g_W8[N_DIM * K_DIM];
__device__ uint8_t g_LUT8[65536];
__device__ unsigned int g_tileCtr;

static __device__ __forceinline__ uint8_t clamp_u8(float v) {
    int c = (int)v;
    c = c < 0 ? 0 : (c > 255 ? 255 : c);
    return (uint8_t)c;
}

__global__ void quantA_kernel(const float* __restrict__ src) {
    int i = blockIdx.x * blockDim.x + threadIdx.x;   // groups of 4
    if (i < M_DIM * K_DIM / 4) {
        float4 v = ((const float4*)src)[i];
        uchar4 b;
        b.x = clamp_u8(v.x); b.y = clamp_u8(v.y);
        b.z = clamp_u8(v.z); b.w = clamp_u8(v.w);
        ((uchar4*)g_A8)[i] = b;
    }
}

__global__ void quantW_kernel(const float* __restrict__ src) {
    int i = blockIdx.x * blockDim.x + threadIdx.x;
    if (i < N_DIM * K_DIM / 4) {
        float4 v = ((const float4*)src)[i];
        uchar4 b;
        b.x = clamp_u8(v.x); b.y = clamp_u8(v.y);
        b.z = clamp_u8(v.z); b.w = clamp_u8(v.w);
        ((uchar4*)g_W8)[i] = b;
    }
}

__global__ void quantLUT_kernel(const int* __restrict__ lut) {
    int i = blockIdx.x * blockDim.x + threadIdx.x;   // groups of 4
    if (i == 0) g_tileCtr = 0;                       // reset queue every launch
    if (i < 65536 / 4) {
        int4 v = ((const int4*)lut)[i];
        uchar4 b;
        b.x = (uint8_t)v.x; b.y = (uint8_t)v.y;
        b.z = (uint8_t)v.z; b.w = (uint8_t)v.w;
        ((uchar4*)g_LUT8)[i] = b;
    }
}

// Index build: ((aword shift)&0xFF00)|w  -> SHF+LOP3 per index.
#define GATHER4(accv, aword, wv0, wv1, wv2, wv3)             \
    do {                                                     \
        uint32_t _i0 = (((aword) << 8)  & 0xFF00u) | (wv0);  \
        uint32_t _i1 = (( aword)        & 0xFF00u) | (wv1);  \
        uint32_t _i2 = (((aword) >> 8)  & 0xFF00u) | (wv2);  \
        uint32_t _i3 = (((aword) >> 16) & 0xFF00u) | (wv3);  \
        accv += sLUT[_i0];                                   \
        accv += sLUT[_i1];                                   \
        accv += sLUT[_i2];                                   \
        accv += sLUT[_i3];                                   \
    } while (0)

// One k-group of 8: a codes from two broadcast words, w codes from two words.
#define KGROUP8(alo, ahi, wlo, whi, accv)                                  \
    do {                                                                   \
        uint32_t _w0 =  (wlo)        & 255u, _w1 = ((wlo) >> 8)  & 255u;   \
        uint32_t _w2 = ((wlo) >> 16) & 255u, _w3 =  (wlo) >> 24;           \
        uint32_t _w4 =  (whi)        & 255u, _w5 = ((whi) >> 8)  & 255u;   \
        uint32_t _w6 = ((whi) >> 16) & 255u, _w7 =  (whi) >> 24;           \
        GATHER4(accv, alo, _w0, _w1, _w2, _w3);                            \
        GATHER4(accv, ahi, _w4, _w5, _w6, _w7);                            \
    } while (0)

// Persistent LUT-GEMM kernel: 456 CTAs, 128 threads, occ 3 -> 12 warps/SM.
__global__ void __launch_bounds__(128, 3)
lut_gemm_kernel(const float* __restrict__ bias,
                float* __restrict__ out) {
    extern __shared__ uint8_t smem[];
    uint8_t* sLUT = smem;                     // 65536 B
    uint8_t* sA   = smem + 65536;             // [2][BM][SA_STRIDE]
    uint8_t* sW   = sA + 2 * SA_BUF;          // [2][BN][SW_STRIDE]
    __shared__ int sTile;

    const int tid  = threadIdx.x;
    const int lane = tid & 31;
    const int warp = tid >> 5;                // 0..3 -> m-group of 8 rows

    // Copy pre-quantized LUT (64KB) into shared ONCE per persistent CTA.
    for (int i = tid; i < 65536 / 16; i += 128) {
        ((uint4*)sLUT)[i] = ((const uint4*)g_LUT8)[i];
    }

    const int mBase = warp * 8;               // warp's first row within tile

    // Staging roles:
    // A: threads 0..63 cover 32 rows x 2 chunks of 16B.
    const int arow   = tid >> 1;
    const int achunk = (tid & 1) * 16;
    uint8_t* sAst = sA + arow * SA_STRIDE + achunk;
    // W: all 128 threads cover 64 rows x 2 chunks of 16B.
    const int wrow   = tid >> 1;
    const int wchunk = (tid & 1) * 16;
    uint8_t* sWst = sW + wrow * SW_STRIDE + wchunk;

    const uint8_t* sArow  = sA + mBase * SA_STRIDE;
    const uint8_t* sWrowA = sW + lane * SW_STRIDE;          // n = n0+lane
    const uint8_t* sWrowB = sW + (lane + 32) * SW_STRIDE;   // n = n0+lane+32

    for (;;) {
        if (tid == 0) sTile = (int)atomicAdd(&g_tileCtr, 1u);
        __syncthreads();                      // broadcast tile; fences smem reuse
        const int tileId = sTile;
        if (tileId >= NUM_TILES) break;       // uniform exit

        const int m0 = (tileId >> 5) * BM;    // 32 tile rows
        const int n0 = (tileId & 31) * BN;    // 32 tile cols

        int accA[8], accB[8];
#pragma unroll
        for (int i = 0; i < 8; i++) { accA[i] = 0; accB[i] = 0; }

        const uint8_t* gAst = g_A8 + ((size_t)(m0 + arow)) * K_DIM + achunk;
        const uint8_t* gWst = g_W8 + ((size_t)(n0 + wrow)) * K_DIM + wchunk;

        // ---- prologue: stage tile 0 into buffer 0 ----
        {
            if (tid < 64) {
                uint4 ra = *(const uint4*)gAst;
                *(uint4*)sAst = ra;
            }
            uint4 rw = *(const uint4*)gWst;
            *(uint4*)sWst = rw;
        }
        __syncthreads();

        for (int t = 0; t < NT; t++) {
            // Prefetch tile t+1 into registers (clamped on last iter).
            const int kn = ((t + 1 < NT) ? (t + 1) : t) * KT;
            uint4 ra_n;
            if (tid < 64) ra_n = *(const uint4*)(gAst + kn);
            uint4 rw_n = *(const uint4*)(gWst + kn);

            const int bufo = (t & 1);
            const uint8_t* sAbuf  = sArow  + bufo * SA_BUF;
            const uint8_t* sWbufA = sWrowA + bufo * SW_BUF;
            const uint8_t* sWbufB = sWrowB + bufo * SW_BUF;

            // Two 16-k halves: keeps live W regs at 8 (wa + wb).
#pragma unroll
            for (int h = 0; h < 2; h++) {
                uint4 wa = *(const uint4*)(sWbufA + h * 16);   // n,    16 k
                uint4 wb = *(const uint4*)(sWbufB + h * 16);   // n+32, 16 k

#pragma unroll
                for (int m = 0; m < 8; m++) {
                    // One warp-uniform LDS.128 broadcast: 16 a-codes, feeds
                    // 32 lookups (16 k x 2 n-columns).
                    uint4 av = *(const uint4*)(sAbuf + m * SA_STRIDE + h * 16);
                    KGROUP8(av.x, av.y, wa.x, wa.y, accA[m]);
                    KGROUP8(av.z, av.w, wa.z, wa.w, accA[m]);
                    KGROUP8(av.x, av.y, wb.x, wb.y, accB[m]);
                    KGROUP8(av.z, av.w, wb.z, wb.w, accB[m]);
                }
            }

            // Stage tile t+1 into the other buffer, then sync.
            const int nbufo = ((t + 1) & 1);
            if (tid < 64) *(uint4*)(sAst + nbufo * SA_BUF) = ra_n;
            *(uint4*)(sWst + nbufo * SW_BUF) = rw_n;
            __syncthreads();
        }

        const float bA = bias[n0 + lane];
        const float bB = bias[n0 + 32 + lane];
#pragma unroll
        for (int m = 0; m < 8; m++) {
            const size_t row = (size_t)(m0 + mBase + m) * N_DIM;
            out[row + n0 + lane]      = (float)accA[m] + bA;
            out[row + n0 + 32 + lane] = (float)accB[m] + bB;
        }
        // loop back: the atomic-broadcast __syncthreads fences buffer reuse
    }
}

extern "C" void kernel_launch(void* const* d_in, const int* in_sizes, int n_in,
                              void* d_out, int out_size) {
    const float* input  = (const float*)d_in[0];  // [M, K] codes as f32
    const float* weight = (const float*)d_in[1];  // [N, K] codes as f32
    const float* bias   = (const float*)d_in[2];  // [N]
    const int*   lut    = (const int*)d_in[3];    // [256*256]
    float* out = (float*)d_out;

    (void)in_sizes; (void)n_in; (void)out_size;

    // Opt-in to >48KB dynamic smem (idempotent; capture-safe)
    cudaFuncSetAttribute((const void*)lut_gemm_kernel,
                         cudaFuncAttributeMaxDynamicSharedMemorySize, SMEM_BYTES);

    quantA_kernel<<<(M_DIM * K_DIM / 4 + 255) / 256, 256>>>(input);
    quantW_kernel<<<(N_DIM * K_DIM / 4 + 255) / 256, 256>>>(weight);
    quantLUT_kernel<<<(65536 / 4 + 255) / 256, 256>>>(lut);  // also resets queue

    lut_gemm_kernel<<<PERSIST_CTAS, 128, SMEM_BYTES>>>(bias, out);
}